// round 16
// baseline (speedup 1.0000x reference)
#include <cuda_runtime.h>
#include <cuda_bf16.h>
#include <math.h>
#include <stdint.h>

#define BB 2
#define SSEQ 2048
#define DD 1024
#define HH 16
#define HD 64
#define FF 4096
#define NL 8
#define NT (BB*SSEQ)

// ---------------- scratch ----------------
__device__ float g_x[NT*DD];
__device__ __nv_bfloat16 g_h_hi[NT*DD];
__device__ __nv_bfloat16 g_h_lo[NT*DD];
__device__ __nv_bfloat16 g_q_hi[NT*DD];
__device__ __nv_bfloat16 g_q_lo[NT*DD];
__device__ __nv_bfloat16 g_kv_hi[NT*2*DD];
__device__ __nv_bfloat16 g_kv_lo[NT*2*DD];
__device__ __nv_bfloat16 g_att_hi[NT*DD];
__device__ __nv_bfloat16 g_att_lo[NT*DD];
__device__ __nv_bfloat16 g_f_hi[NT*FF];
__device__ __nv_bfloat16 g_f_lo[NT*FF];
__device__ __nv_bfloat16 g_wqkv_h[NL*3*DD*DD];
__device__ __nv_bfloat16 g_wqkv_l[NL*3*DD*DD];
__device__ __nv_bfloat16 g_wo_h[NL*DD*DD];
__device__ __nv_bfloat16 g_wo_l[NL*DD*DD];
__device__ __nv_bfloat16 g_w1_h[NL*DD*FF];
__device__ __nv_bfloat16 g_w1_l[NL*DD*FF];
__device__ __nv_bfloat16 g_w2_h[NL*FF*DD];
__device__ __nv_bfloat16 g_w2_l[NL*FF*DD];

// ---------------- helpers ----------------
__device__ __forceinline__ float softplus_f(float x) {
    return fmaxf(x, 0.0f) + log1pf(expf(-fabsf(x)));
}
__device__ __forceinline__ uint32_t smem_u32(const void* p) {
    uint32_t a;
    asm("{ .reg .u64 t; cvta.to.shared.u64 t, %1; cvt.u32.u64 %0, t; }" : "=r"(a) : "l"(p));
    return a;
}
__device__ __forceinline__ void cp16(uint32_t s, const void* g) {
    asm volatile("cp.async.cg.shared.global [%0], [%1], 16;" :: "r"(s), "l"(g));
}
#define CP_COMMIT() asm volatile("cp.async.commit_group;")
#define CP_WAIT0()  asm volatile("cp.async.wait_group 0;")
#define CP_WAIT1()  asm volatile("cp.async.wait_group 1;")
#define CP_WAIT2()  asm volatile("cp.async.wait_group 2;")
__device__ __forceinline__ void split2(float a, float b, uint32_t& hi, uint32_t& lo) {
    __nv_bfloat162 h = __floats2bfloat162_rn(a, b);
    float ra = a - __bfloat162float(h.x);
    float rb = b - __bfloat162float(h.y);
    __nv_bfloat162 l = __floats2bfloat162_rn(ra, rb);
    hi = *(uint32_t*)&h; lo = *(uint32_t*)&l;
}
#define LDMX4(R0,R1,R2,R3,ADDR) \
    asm volatile("ldmatrix.sync.aligned.m8n8.x4.shared.b16 {%0,%1,%2,%3}, [%4];" \
        : "=r"(R0),"=r"(R1),"=r"(R2),"=r"(R3) : "r"(ADDR))
#define LDMX4T(R0,R1,R2,R3,ADDR) \
    asm volatile("ldmatrix.sync.aligned.m8n8.x4.trans.shared.b16 {%0,%1,%2,%3}, [%4];" \
        : "=r"(R0),"=r"(R1),"=r"(R2),"=r"(R3) : "r"(ADDR))
#define MMA16816(C, A, B0, B1) \
    asm volatile("mma.sync.aligned.m16n8k16.row.col.f32.bf16.bf16.f32 " \
        "{%0,%1,%2,%3}, {%4,%5,%6,%7}, {%8,%9}, {%0,%1,%2,%3};" \
        : "+f"((C)[0]),"+f"((C)[1]),"+f"((C)[2]),"+f"((C)[3]) \
        : "r"((A)[0]),"r"((A)[1]),"r"((A)[2]),"r"((A)[3]), "r"(B0),"r"(B1))

// ---------------- weight transpose + split (shared body) --------------------
__device__ __forceinline__ void wconv_tile(const float* __restrict__ W,
                                           __nv_bfloat16* __restrict__ oh,
                                           __nv_bfloat16* __restrict__ ol,
                                           int K, int M, int m0, int k0)
{
    __shared__ float t[32][33];
    int tx = threadIdx.x, ty = threadIdx.y;   // 32 x 8
    #pragma unroll
    for (int j = 0; j < 4; j++)
        t[ty + 8*j][tx] = W[(size_t)(k0 + ty + 8*j) * M + m0 + tx];
    __syncthreads();
    #pragma unroll
    for (int j = 0; j < 4; j++) {
        float v = t[tx][ty + 8*j];
        int m = m0 + ty + 8*j, k = k0 + tx;
        __nv_bfloat16 h = __float2bfloat16(v);
        oh[(size_t)m * K + k] = h;
        ol[(size_t)m * K + k] = __float2bfloat16(v - __bfloat162float(h));
    }
}

// merged wq+wkv+wo (grid: x = 4096 flat tiles, z = layer)
__global__ void wconv_a_kernel(const float* __restrict__ wq,
                               const float* __restrict__ wkv,
                               const float* __restrict__ wo,
                               __nv_bfloat16* __restrict__ qkvh,
                               __nv_bfloat16* __restrict__ qkvl,
                               __nv_bfloat16* __restrict__ woh,
                               __nv_bfloat16* __restrict__ wol)
{
    int l = blockIdx.z, bx = blockIdx.x;
    if (bx < 3072) {
        // packed qkv: 96 m-tiles x 32 k-tiles
        int mt = bx >> 5, kt = bx & 31;
        __nv_bfloat16* oh = qkvh + (size_t)l * 3 * DD * DD;
        __nv_bfloat16* ol = qkvl + (size_t)l * 3 * DD * DD;
        if (mt < 32)
            wconv_tile(wq + (size_t)l * DD * DD, oh, ol, DD, DD, mt * 32, kt * 32);
        else
            wconv_tile(wkv + (size_t)l * DD * 2 * DD, oh + (size_t)DD * DD,
                       ol + (size_t)DD * DD, DD, 2 * DD, (mt - 32) * 32, kt * 32);
    } else {
        int idx = bx - 3072;                 // wo: 32 x 32 tiles
        int mt = idx >> 5, kt = idx & 31;
        size_t off = (size_t)l * DD * DD;
        wconv_tile(wo + off, woh + off, wol + off, DD, DD, mt * 32, kt * 32);
    }
}

// merged w1+w2 (grid: x = 4096 flat tiles, z in [0,16))
__global__ void wconv_b_kernel(const float* __restrict__ w1,
                               const float* __restrict__ w2,
                               __nv_bfloat16* __restrict__ w1h,
                               __nv_bfloat16* __restrict__ w1l,
                               __nv_bfloat16* __restrict__ w2h,
                               __nv_bfloat16* __restrict__ w2l)
{
    int z = blockIdx.z, bx = blockIdx.x;
    if (z < NL) {
        int mt = bx & 127, kt = bx >> 7;
        size_t off = (size_t)z * DD * FF;
        wconv_tile(w1 + off, w1h + off, w1l + off, DD, FF, mt * 32, kt * 32);
    } else {
        int mt = bx & 31, kt = bx >> 5;
        size_t off = (size_t)(z - NL) * FF * DD;
        wconv_tile(w2 + off, w2h + off, w2l + off, FF, DD, mt * 32, kt * 32);
    }
}

// ---------------- LayerNorms ----------------
#define LN_REDUCE() \
    _Pragma("unroll") \
    for (int o = 16; o > 0; o >>= 1) { \
        s  += __shfl_xor_sync(0xffffffffu, s,  o); \
        sq += __shfl_xor_sync(0xffffffffu, sq, o); } \
    if ((tid & 31) == 0) { sm1[tid >> 5] = s; sm2[tid >> 5] = sq; } \
    __syncthreads(); \
    if (tid < 32) { \
        s  = (tid < 8) ? sm1[tid] : 0.0f; \
        sq = (tid < 8) ? sm2[tid] : 0.0f; \
        _Pragma("unroll") \
        for (int o = 4; o > 0; o >>= 1) { \
            s  += __shfl_xor_sync(0xffffffffu, s,  o); \
            sq += __shfl_xor_sync(0xffffffffu, sq, o); } \
        if (tid == 0) { sm1[0] = s; sm2[0] = sq; } } \
    __syncthreads();

__global__ void ln_kernel(const float* __restrict__ in, const float* __restrict__ gamma,
                          const float* __restrict__ beta, float* __restrict__ out)
{
    int row = blockIdx.x, tid = threadIdx.x;
    float4 v = *(const float4*)(in + (size_t)row * DD + tid * 4);
    float s  = v.x + v.y + v.z + v.w;
    float sq = v.x*v.x + v.y*v.y + v.z*v.z + v.w*v.w;
    __shared__ float sm1[8], sm2[8];
    LN_REDUCE();
    float mean = sm1[0] * (1.0f / DD);
    float var  = sm2[0] * (1.0f / DD) - mean * mean;
    float rs   = rsqrtf(var + 1e-3f);
    float4 g  = *(const float4*)(gamma + tid * 4);
    float4 be = *(const float4*)(beta  + tid * 4);
    float4 o4;
    o4.x = (v.x - mean) * rs * g.x + be.x;
    o4.y = (v.y - mean) * rs * g.y + be.y;
    o4.z = (v.z - mean) * rs * g.z + be.z;
    o4.w = (v.w - mean) * rs * g.w + be.w;
    *(float4*)(out + (size_t)row * DD + tid * 4) = o4;
}

__global__ void ln_bf16_kernel(const float* __restrict__ in, const float* __restrict__ gamma,
                               const float* __restrict__ beta,
                               __nv_bfloat16* __restrict__ ohi, __nv_bfloat16* __restrict__ olo)
{
    int row = blockIdx.x, tid = threadIdx.x;
    float4 v = *(const float4*)(in + (size_t)row * DD + tid * 4);
    float s  = v.x + v.y + v.z + v.w;
    float sq = v.x*v.x + v.y*v.y + v.z*v.z + v.w*v.w;
    __shared__ float sm1[8], sm2[8];
    LN_REDUCE();
    float mean = sm1[0] * (1.0f / DD);
    float var  = sm2[0] * (1.0f / DD) - mean * mean;
    float rs   = rsqrtf(var + 1e-3f);
    float4 g  = *(const float4*)(gamma + tid * 4);
    float4 be = *(const float4*)(beta  + tid * 4);
    float a = (v.x - mean) * rs * g.x + be.x;
    float b = (v.y - mean) * rs * g.y + be.y;
    float c = (v.z - mean) * rs * g.z + be.z;
    float d = (v.w - mean) * rs * g.w + be.w;
    uint2 uh, ul;
    split2(a, b, uh.x, ul.x);
    split2(c, d, uh.y, ul.y);
    size_t off = (size_t)row * DD + tid * 4;
    *(uint2*)(ohi + off) = uh;
    *(uint2*)(olo + off) = ul;
}

// ---------------- HMMA split-bf16 GEMM, 128x128, cp.async 3-stage -----------
#define TSTR 72
#define SA_H 0
#define SA_L 18432
#define SB_H 36864
#define SB_L 55296
#define TG_STAGE 73728
#define TG_SMEM (3*TG_STAGE)        // 221184

#define TG_LOADS(kb, stg) do {                                            \
    uint32_t base_ = sb + (uint32_t)(stg) * TG_STAGE;                     \
    _Pragma("unroll")                                                     \
    for (int u = 0; u < 4; u++) {                                         \
        int idx = tid + u * 256;                                          \
        int r = idx >> 3, c = (idx & 7) * 8;                              \
        size_t g = (size_t)(m0 + r) * K + (kb) + c;                       \
        uint32_t so = (uint32_t)(r * TSTR + c) * 2;                       \
        cp16(base_ + SA_H + so, Ah + g);                                  \
        cp16(base_ + SA_L + so, Al + g);                                  \
        size_t gb = (size_t)(n0 + r) * K + (kb) + c;                      \
        cp16(base_ + SB_H + so, Bh + gb);                                 \
        cp16(base_ + SB_L + so, Bl + gb);                                 \
    }                                                                     \
} while (0)

__global__ void __launch_bounds__(256) tgemm_kernel(
    const __nv_bfloat16* __restrict__ Ah, const __nv_bfloat16* __restrict__ Al,
    const __nv_bfloat16* __restrict__ Bh, const __nv_bfloat16* __restrict__ Bl,
    const float* __restrict__ bias, const float* __restrict__ bias2,
    const float* __restrict__ res,
    float* __restrict__ C, __nv_bfloat16* __restrict__ Chi,
    __nv_bfloat16* __restrict__ Clo, __nv_bfloat16* __restrict__ Chi2,
    __nv_bfloat16* __restrict__ Clo2, int K, int M, int epi)
{
    extern __shared__ char smem[];
    uint32_t sb = smem_u32(smem);
    int tid = threadIdx.x, lane = tid & 31, w = tid >> 5;
    int wm = w & 3, wn = w >> 2;
    int m0 = blockIdx.y * 128, n0 = blockIdx.x * 128;

    float acc[2][8][4];
    #pragma unroll
    for (int i = 0; i < 2; i++)
        #pragma unroll
        for (int j = 0; j < 8; j++)
            #pragma unroll
            for (int c = 0; c < 4; c++) acc[i][j][c] = 0.0f;

    uint32_t a_off = (uint32_t)((wm*32 + (lane & 15))*TSTR + ((lane >> 4) << 3)) * 2;
    uint32_t b_off = (uint32_t)((wn*64 + ((lane >> 4) << 3) + (lane & 7))*TSTR
                                + (((lane >> 3) & 1) << 3)) * 2;

    int nch = K >> 6;
    TG_LOADS(0, 0);
    CP_COMMIT();
    if (nch > 1) { TG_LOADS(64, 1); CP_COMMIT(); }

    for (int kc = 0; kc < nch; kc++) {
        if (kc + 2 < nch) { TG_LOADS((kc + 2)*64, (kc + 2) % 3); CP_COMMIT(); CP_WAIT2(); }
        else if (kc + 1 < nch) { CP_WAIT1(); }
        else { CP_WAIT0(); }
        __syncthreads();

        uint32_t stb = sb + (uint32_t)(kc % 3) * TG_STAGE;
        #pragma unroll
        for (int ks = 0; ks < 4; ks++) {
            uint32_t kb = (uint32_t)(ks * 16) * 2;
            uint32_t ah[2][4], al[2][4];
            #pragma unroll
            for (int i = 0; i < 2; i++) {
                uint32_t aa = stb + SA_H + a_off + (uint32_t)(i*16*TSTR)*2 + kb;
                LDMX4(ah[i][0], ah[i][1], ah[i][2], ah[i][3], aa);
                LDMX4(al[i][0], al[i][1], al[i][2], al[i][3], aa + (SA_L - SA_H));
            }
            #pragma unroll
            for (int p = 0; p < 4; p++) {
                uint32_t bh[4], bl[4];
                uint32_t ba = stb + SB_H + b_off + (uint32_t)(p*16*TSTR)*2 + kb;
                LDMX4(bh[0], bh[1], bh[2], bh[3], ba);
                LDMX4(bl[0], bl[1], bl[2], bl[3], ba + (SB_L - SB_H));
                #pragma unroll
                for (int i = 0; i < 2; i++)
                    #pragma unroll
                    for (int sub = 0; sub < 2; sub++) {
                        int j = p * 2 + sub;
                        MMA16816(acc[i][j], ah[i], bh[sub*2], bh[sub*2+1]);
                        MMA16816(acc[i][j], ah[i], bl[sub*2], bl[sub*2+1]);
                        MMA16816(acc[i][j], al[i], bh[sub*2], bh[sub*2+1]);
                    }
            }
        }
        __syncthreads();
    }

    // ---- epilogue ----
    #pragma unroll
    for (int i = 0; i < 2; i++) {
        int row0 = m0 + wm*32 + i*16 + (lane >> 2);
        #pragma unroll
        for (int j = 0; j < 8; j++) {
            int col = n0 + wn*64 + (j >> 1)*16 + (j & 1)*8 + (lane & 3)*2;
            #pragma unroll
            for (int half = 0; half < 2; half++) {
                int r = row0 + half*8;
                float o0 = acc[i][j][half*2+0];
                float o1 = acc[i][j][half*2+1];
                if (epi == 4) {
                    uint32_t uh, ul;
                    if (col < DD) {
                        float2 b2 = *(const float2*)(bias + col);
                        o0 = (o0 + b2.x) * 0.125f;
                        o1 = (o1 + b2.y) * 0.125f;
                        split2(o0, o1, uh, ul);
                        size_t off = (size_t)r * DD + col;
                        *(uint32_t*)(Chi + off) = uh;
                        *(uint32_t*)(Clo + off) = ul;
                    } else {
                        float2 b2 = *(const float2*)(bias2 + (col - DD));
                        o0 += b2.x; o1 += b2.y;
                        split2(o0, o1, uh, ul);
                        size_t off = (size_t)r * (2*DD) + (col - DD);
                        *(uint32_t*)(Chi2 + off) = uh;
                        *(uint32_t*)(Clo2 + off) = ul;
                    }
                } else if (epi == 1) {
                    float2 b2 = *(const float2*)(bias + col);
                    o0 = softplus_f(o0 + b2.x);
                    o1 = softplus_f(o1 + b2.y);
                    uint32_t uh, ul;
                    split2(o0, o1, uh, ul);
                    size_t off = (size_t)r * M + col;
                    *(uint32_t*)(Chi + off) = uh;
                    *(uint32_t*)(Clo + off) = ul;
                } else {
                    float2 b2 = *(const float2*)(bias + col);
                    size_t off = (size_t)r * M + col;
                    float2 r2 = *(const float2*)(res + off);
                    float2 o = {o0 + b2.x + r2.x, o1 + b2.y + r2.y};
                    *(float2*)(C + off) = o;
                }
            }
        }
    }
}

// ---------------- fused flash attention (R10) ----------------
#define FTSTR 72
#define FQ_H 0
#define FQ_L 18432
#define FKV0 36864
#define FKV_STAGE 36864
#define FK_H 0
#define FK_L 9216
#define FV_H 18432
#define FV_L 27648
#define F_SMEM (FKV0 + 2*FKV_STAGE)

#define F_LOADKV(kt, stg) do {                                            \
    uint32_t base_ = sb + FKV0 + (uint32_t)(stg) * FKV_STAGE;             \
    _Pragma("unroll")                                                     \
    for (int u = 0; u < 2; u++) {                                         \
        int idx = tid + u * 256;                                          \
        int r = idx >> 3, c = (idx & 7) * 8;                              \
        size_t gk = (size_t)((kt) * 64 + r) * (2 * DD) + c;               \
        uint32_t so = (uint32_t)(r * FTSTR + c) * 2;                      \
        cp16(base_ + FK_H + so, kb_h + gk);                               \
        cp16(base_ + FK_L + so, kb_l + gk);                               \
        cp16(base_ + FV_H + so, kb_h + gk + DD);                          \
        cp16(base_ + FV_L + so, kb_l + gk + DD);                          \
    }                                                                     \
} while (0)

__global__ void __launch_bounds__(256) fattn_kernel(
    const __nv_bfloat16* __restrict__ Qh_, const __nv_bfloat16* __restrict__ Ql_,
    const __nv_bfloat16* __restrict__ KVh, const __nv_bfloat16* __restrict__ KVl,
    __nv_bfloat16* __restrict__ Ohi, __nv_bfloat16* __restrict__ Olo)
{
    extern __shared__ char smem[];
    uint32_t sb = smem_u32(smem);
    int tid = threadIdx.x, lane = tid & 31, w = tid >> 5;
    int qtile = gridDim.x - 1 - blockIdx.x;
    int bh = blockIdx.y;
    int b = bh >> 4, h = bh & 15;
    int q0 = qtile * 128;

    const __nv_bfloat16* kb_h = KVh + (size_t)b * SSEQ * 2 * DD + h * HD;
    const __nv_bfloat16* kb_l = KVl + (size_t)b * SSEQ * 2 * DD + h * HD;

    F_LOADKV(0, 0);
    CP_COMMIT();
    #pragma unroll
    for (int u = 0; u < 4; u++) {
        int idx = tid + u * 256;
        int r = idx >> 3, c = (idx & 7) * 8;
        size_t g = ((size_t)b * SSEQ + q0 + r) * DD + h * HD + c;
        uint32_t so = (uint32_t)(r * FTSTR + c) * 2;
        *(uint4*)(smem + FQ_H + so) = *(const uint4*)(Qh_ + g);
        *(uint4*)(smem + FQ_L + so) = *(const uint4*)(Ql_ + g);
    }
    __syncthreads();

    uint32_t qh[4][4], ql[4][4];
    uint32_t a_off = (uint32_t)((w * 16 + (lane & 15)) * FTSTR + ((lane >> 4) << 3)) * 2;
    #pragma unroll
    for (int ks = 0; ks < 4; ks++) {
        LDMX4(qh[ks][0], qh[ks][1], qh[ks][2], qh[ks][3], sb + FQ_H + a_off + ks * 32);
        LDMX4(ql[ks][0], ql[ks][1], ql[ks][2], ql[ks][3], sb + FQ_L + a_off + ks * 32);
    }

    float m0 = -1e30f, m1 = -1e30f, l0 = 0.0f, l1 = 0.0f;
    float o[8][4];
    #pragma unroll
    for (int j = 0; j < 8; j++)
        #pragma unroll
        for (int c = 0; c < 4; c++) o[j][c] = 0.0f;

    float slope = exp2f(-0.5f * (float)(h + 1));
    int row0 = q0 + w * 16 + (lane >> 2);
    int warp_rmax = q0 + w * 16 + 15;
    int nkt = (q0 + 127) / 64 + 1;

    for (int kt = 0; kt < nkt; kt++) {
        if (kt + 1 < nkt) { F_LOADKV(kt + 1, (kt + 1) & 1); CP_COMMIT(); CP_WAIT1(); }
        else             { CP_WAIT0(); }
        __syncthreads();
        uint32_t stb = sb + FKV0 + (uint32_t)(kt & 1) * FKV_STAGE;

        if (kt * 64 <= warp_rmax) {
            float S[8][4];
            #pragma unroll
            for (int j = 0; j < 8; j++)
                #pragma unroll
                for (int c = 0; c < 4; c++) S[j][c] = 0.0f;
            #pragma unroll
            for (int ks = 0; ks < 4; ks++) {
                #pragma unroll
                for (int p = 0; p < 4; p++) {
                    uint32_t kh[4], kl[4];
                    uint32_t boff = (uint32_t)((p*16 + ((lane >> 4) << 3) + (lane & 7)) * FTSTR
                                               + (((lane >> 3) & 1) << 3)) * 2 + ks * 32;
                    LDMX4(kh[0], kh[1], kh[2], kh[3], stb + FK_H + boff);
                    LDMX4(kl[0], kl[1], kl[2], kl[3], stb + FK_L + boff);
                    MMA16816(S[p*2+0], qh[ks], kh[0], kh[1]);
                    MMA16816(S[p*2+1], qh[ks], kh[2], kh[3]);
                    MMA16816(S[p*2+0], qh[ks], kl[0], kl[1]);
                    MMA16816(S[p*2+1], qh[ks], kl[2], kl[3]);
                    MMA16816(S[p*2+0], ql[ks], kh[0], kh[1]);
                    MMA16816(S[p*2+1], ql[ks], kh[2], kh[3]);
                }
            }
            #pragma unroll
            for (int j = 0; j < 8; j++) {
                int col = kt * 64 + j * 8 + (lane & 3) * 2;
                S[j][0] = (col     <= row0)     ? S[j][0] + slope*(float)(col     - row0)     : -1e30f;
                S[j][1] = (col + 1 <= row0)     ? S[j][1] + slope*(float)(col + 1 - row0)     : -1e30f;
                S[j][2] = (col     <= row0 + 8) ? S[j][2] + slope*(float)(col     - row0 - 8) : -1e30f;
                S[j][3] = (col + 1 <= row0 + 8) ? S[j][3] + slope*(float)(col + 1 - row0 - 8) : -1e30f;
            }
            float rm0 = -1e30f, rm1 = -1e30f;
            #pragma unroll
            for (int j = 0; j < 8; j++) {
                rm0 = fmaxf(rm0, fmaxf(S[j][0], S[j][1]));
                rm1 = fmaxf(rm1, fmaxf(S[j][2], S[j][3]));
            }
            rm0 = fmaxf(rm0, __shfl_xor_sync(0xffffffffu, rm0, 1));
            rm0 = fmaxf(rm0, __shfl_xor_sync(0xffffffffu, rm0, 2));
            rm1 = fmaxf(rm1, __shfl_xor_sync(0xffffffffu, rm1, 1));
            rm1 = fmaxf(rm1, __shfl_xor_sync(0xffffffffu, rm1, 2));
            float mn0 = fmaxf(m0, rm0), mn1 = fmaxf(m1, rm1);
            float al0 = expf(m0 - mn0), al1 = expf(m1 - mn1);
            m0 = mn0; m1 = mn1;
            float ps0 = 0.0f, ps1 = 0.0f;
            #pragma unroll
            for (int j = 0; j < 8; j++) {
                S[j][0] = expf(S[j][0] - m0); S[j][1] = expf(S[j][1] - m0);
                S[j][2] = expf(S[j][2] - m1); S[j][3] = expf(S[j][3] - m1);
                ps0 += S[j][0] + S[j][1];
                ps1 += S[j][2] + S[j][3];
            }
            l0 = l0 * al0 + ps0;
            l1 = l1 * al1 + ps1;
            #pragma unroll
            for (int j = 0; j < 8; j++) {
                o[j][0] *= al0; o[j][1] *= al0;
                o[j][2] *= al1; o[j][3] *= al1;
            }
            #pragma unroll
            for (int j = 0; j < 4; j++) {
                uint32_t ph[4], pl[4];
                split2(S[2*j  ][0], S[2*j  ][1], ph[0], pl[0]);
                split2(S[2*j  ][2], S[2*j  ][3], ph[1], pl[1]);
                split2(S[2*j+1][0], S[2*j+1][1], ph[2], pl[2]);
                split2(S[2*j+1][2], S[2*j+1][3], ph[3], pl[3]);
                #pragma unroll
                for (int pp = 0; pp < 4; pp++) {
                    uint32_t vh[4], vl[4];
                    uint32_t voff = (uint32_t)((j*16 + (lane & 15)) * FTSTR
                                               + pp*16 + ((lane >> 4) << 3)) * 2;
                    LDMX4T(vh[0], vh[1], vh[2], vh[3], stb + FV_H + voff);
                    LDMX4T(vl[0], vl[1], vl[2], vl[3], stb + FV_L + voff);
                    MMA16816(o[pp*2+0], ph, vh[0], vh[1]);
                    MMA16816(o[pp*2+1], ph, vh[2], vh[3]);
                    MMA16816(o[pp*2+0], ph, vl[0], vl[1]);
                    MMA16816(o[pp*2+1], ph, vl[2], vl[3]);
                    MMA16816(o[pp*2+0], pl, vh[0], vh[1]);
                    MMA16816(o[pp*2+1], pl, vh[2], vh[3]);
                }
            }
        }
        __syncthreads();
    }

    l0 += __shfl_xor_sync(0xffffffffu, l0, 1);
    l0 += __shfl_xor_sync(0xffffffffu, l0, 2);
    l1 += __shfl_xor_sync(0xffffffffu, l1, 1);
    l1 += __shfl_xor_sync(0xffffffffu, l1, 2);
    float i0 = 1.0f / l0, i1 = 1.0f / l1;

    size_t gr0 = (size_t)b * SSEQ + q0 + w * 16 + (lane >> 2);
    #pragma unroll
    for (int j = 0; j < 8; j++) {
        int col = h * HD + j * 8 + (lane & 3) * 2;
        uint32_t uh, ul;
        split2(o[j][0] * i0, o[j][1] * i0, uh, ul);
        *(uint32_t*)(Ohi + gr0 * DD + col) = uh;
        *(uint32_t*)(Olo + gr0 * DD + col) = ul;
        split2(o[j][2] * i1, o[j][3] * i1, uh, ul);
        *(uint32_t*)(Ohi + (gr0 + 8) * DD + col) = uh;
        *(uint32_t*)(Olo + (gr0 + 8) * DD + col) = ul;
    }
}

// ---------------- host ----------------
extern "C" void kernel_launch(void* const* d_in, const int* in_sizes, int n_in,
                              void* d_out, int out_size)
{
    const float *ts, *fg, *fb, *wq, *bq, *wkv, *bkv, *wo, *bo,
                *w1, *b1, *w2, *b2, *ag, *ab, *ffg, *ffb;
    if (in_sizes[1] == 1024) {
        ts  = (const float*)d_in[0];
        fg  = (const float*)d_in[1];  fb  = (const float*)d_in[2];
        wq  = (const float*)d_in[3];  bq  = (const float*)d_in[4];
        wkv = (const float*)d_in[5];  bkv = (const float*)d_in[6];
        wo  = (const float*)d_in[7];  bo  = (const float*)d_in[8];
        w1  = (const float*)d_in[9];  b1  = (const float*)d_in[10];
        w2  = (const float*)d_in[11]; b2  = (const float*)d_in[12];
        ag  = (const float*)d_in[13]; ab  = (const float*)d_in[14];
        ffg = (const float*)d_in[15]; ffb = (const float*)d_in[16];
    } else {
        ts  = (const float*)d_in[0];
        wq  = (const float*)d_in[1];  bq  = (const float*)d_in[2];
        wkv = (const float*)d_in[3];  bkv = (const float*)d_in[4];
        wo  = (const float*)d_in[5];  bo  = (const float*)d_in[6];
        w1  = (const float*)d_in[7];  b1  = (const float*)d_in[8];
        w2  = (const float*)d_in[9];  b2  = (const float*)d_in[10];
        ag  = (const float*)d_in[11]; ab  = (const float*)d_in[12];
        ffg = (const float*)d_in[13]; ffb = (const float*)d_in[14];
        fg  = (const float*)d_in[15]; fb  = (const float*)d_in[16];
    }

    float *x;
    __nv_bfloat16 *hh, *hl, *qh_, *ql_, *kvh, *kvl, *ath, *atl, *fh, *fl;
    __nv_bfloat16 *wqkvh, *wqkvl, *woh, *wol, *w1h, *w1l, *w2h, *w2l;
    cudaGetSymbolAddress((void**)&x,    g_x);
    cudaGetSymbolAddress((void**)&hh,   g_h_hi);
    cudaGetSymbolAddress((void**)&hl,   g_h_lo);
    cudaGetSymbolAddress((void**)&qh_,  g_q_hi);
    cudaGetSymbolAddress((void**)&ql_,  g_q_lo);
    cudaGetSymbolAddress((void**)&kvh,  g_kv_hi);
    cudaGetSymbolAddress((void**)&kvl,  g_kv_lo);
    cudaGetSymbolAddress((void**)&ath,  g_att_hi);
    cudaGetSymbolAddress((void**)&atl,  g_att_lo);
    cudaGetSymbolAddress((void**)&fh,   g_f_hi);
    cudaGetSymbolAddress((void**)&fl,   g_f_lo);
    cudaGetSymbolAddress((void**)&wqkvh, g_wqkv_h);
    cudaGetSymbolAddress((void**)&wqkvl, g_wqkv_l);
    cudaGetSymbolAddress((void**)&woh,  g_wo_h);
    cudaGetSymbolAddress((void**)&wol,  g_wo_l);
    cudaGetSymbolAddress((void**)&w1h,  g_w1_h);
    cudaGetSymbolAddress((void**)&w1l,  g_w1_l);
    cudaGetSymbolAddress((void**)&w2h,  g_w2_h);
    cudaGetSymbolAddress((void**)&w2l,  g_w2_l);

    cudaFuncSetAttribute(tgemm_kernel,
                         cudaFuncAttributeMaxDynamicSharedMemorySize, TG_SMEM);
    cudaFuncSetAttribute(fattn_kernel,
                         cudaFuncAttributeMaxDynamicSharedMemorySize, F_SMEM);

    // item #1: residual init (memcpy)
    cudaMemcpyAsync(x, ts, sizeof(float)*(size_t)NT*DD, cudaMemcpyDeviceToDevice, 0);

    dim3 blk(32, 8);
    // items #2-#3: all weight conversions in two launches
    wconv_a_kernel<<<dim3(4096, 1, NL), blk>>>(wq, wkv, wo, wqkvh, wqkvl, woh, wol);
    wconv_b_kernel<<<dim3(4096, 1, 2*NL), blk>>>(w1, w2, w1h, w1l, w2h, w2l);

    for (int l = 0; l < NL; l++) {
        // item #4 on first iteration: layer-0 LN
        ln_bf16_kernel<<<NT, 256>>>(x, ag + (size_t)l*DD, ab + (size_t)l*DD, hh, hl);
        // item #5 on first iteration: QKV tgemm -> captured by ncu
        tgemm_kernel<<<dim3(3*DD/128, NT/128), 256, TG_SMEM>>>(
            hh, hl, wqkvh + (size_t)l*3*DD*DD, wqkvl + (size_t)l*3*DD*DD,
            bq + (size_t)l*DD, bkv + (size_t)l*2*DD, nullptr,
            nullptr, qh_, ql_, kvh, kvl, DD, 3*DD, 4);
        fattn_kernel<<<dim3(SSEQ/128, BB*HH), 256, F_SMEM>>>(
            qh_, ql_, kvh, kvl, ath, atl);
        tgemm_kernel<<<dim3(DD/128, NT/128), 256, TG_SMEM>>>(
            ath, atl, woh + (size_t)l*DD*DD, wol + (size_t)l*DD*DD,
            bo + (size_t)l*DD, nullptr, x,
            x, nullptr, nullptr, nullptr, nullptr, DD, DD, 2);
        ln_bf16_kernel<<<NT, 256>>>(x, ffg + (size_t)l*DD, ffb + (size_t)l*DD, hh, hl);
        tgemm_kernel<<<dim3(FF/128, NT/128), 256, TG_SMEM>>>(
            hh, hl, w1h + (size_t)l*DD*FF, w1l + (size_t)l*DD*FF,
            b1 + (size_t)l*FF, nullptr, nullptr,
            nullptr, fh, fl, nullptr, nullptr, DD, FF, 1);
        tgemm_kernel<<<dim3(DD/128, NT/128), 256, TG_SMEM>>>(
            fh, fl, w2h + (size_t)l*FF*DD, w2l + (size_t)l*FF*DD,
            b2 + (size_t)l*DD, nullptr, x,
            x, nullptr, nullptr, nullptr, nullptr, FF, DD, 2);
    }

    ln_kernel<<<NT, 256>>>(x, fg, fb, (float*)d_out);
}